// round 1
// baseline (speedup 1.0000x reference)
#include <cuda_runtime.h>
#include <math.h>

#define BATCH 512
#define NP    64          // feature positions
#define CIN   512
#define HID   512
#define EMB   512
#define NCLS  96
#define TT    30

// ---------------- scratch (device globals; no allocations) ----------------
__device__ float g_feats[(size_t)BATCH * NP * HID];   // 64 MB, fits L2
__device__ float g_emb[(size_t)TT * BATCH * EMB];     // 31.5 MB
__device__ float g_h[BATCH * HID];
__device__ float g_c[BATCH * HID];
__device__ float g_logits[BATCH * HID];
__device__ float g_a[BATCH * HID];
__device__ float g_ctx[BATCH * HID];
__device__ float g_x[BATCH * HID];
__device__ float g_gates[BATCH * 4 * HID];
__device__ float g_Wg[(size_t)4 * HID * (HID + HID)]; // [2048, 1024] = [Wih | Whh]
__device__ float g_bg[4 * HID];

// ---------------- generic dual-source fp32 GEMM: C = A @ B^T + bias -------
// A is logically [M, K] split along K: cols [0,K1) from A1 (row stride lda1),
// cols [K1,K) from A2 (row stride lda2). B is [N, K] row-major.
template <int BM, int BN, int BK, int TM, int TN>
__global__ void gemm_bias_kernel(const float* __restrict__ A1, int lda1, int K1,
                                 const float* __restrict__ A2, int lda2,
                                 int K,
                                 const float* __restrict__ B,
                                 const float* __restrict__ bias,
                                 float* __restrict__ C, int ldc)
{
    constexpr int THREADS = (BM / TM) * (BN / TN);
    constexpr int BKv = BK / 4;
    __shared__ float As[BK][BM];
    __shared__ float Bs[BK][BN];

    const int bm = blockIdx.y * BM;
    const int bn = blockIdx.x * BN;
    const int tid = threadIdx.x;
    const int tcol = tid % (BN / TN);
    const int trow = tid / (BN / TN);

    float acc[TM][TN];
#pragma unroll
    for (int i = 0; i < TM; i++)
#pragma unroll
        for (int j = 0; j < TN; j++) acc[i][j] = 0.f;

    for (int k0 = 0; k0 < K; k0 += BK) {
        const float* Ap;
        int lda, kc;
        if (k0 < K1) { Ap = A1; lda = lda1; kc = k0; }
        else         { Ap = A2; lda = lda2; kc = k0 - K1; }

#pragma unroll
        for (int i = 0; i < (BM * BKv) / THREADS; i++) {
            int idx = tid + i * THREADS;
            int r = idx / BKv, c = idx % BKv;
            float4 v = *(const float4*)(Ap + (size_t)(bm + r) * lda + kc + c * 4);
            As[c * 4 + 0][r] = v.x; As[c * 4 + 1][r] = v.y;
            As[c * 4 + 2][r] = v.z; As[c * 4 + 3][r] = v.w;
        }
#pragma unroll
        for (int i = 0; i < (BN * BKv) / THREADS; i++) {
            int idx = tid + i * THREADS;
            int r = idx / BKv, c = idx % BKv;
            float4 v = *(const float4*)(B + (size_t)(bn + r) * K + k0 + c * 4);
            Bs[c * 4 + 0][r] = v.x; Bs[c * 4 + 1][r] = v.y;
            Bs[c * 4 + 2][r] = v.z; Bs[c * 4 + 3][r] = v.w;
        }
        __syncthreads();

#pragma unroll
        for (int kk = 0; kk < BK; kk++) {
            float4 av = *(const float4*)&As[kk][trow * TM];
            float4 bv = *(const float4*)&Bs[kk][tcol * TN];
            float a_[4] = {av.x, av.y, av.z, av.w};
            float b_[4] = {bv.x, bv.y, bv.z, bv.w};
#pragma unroll
            for (int i = 0; i < TM; i++)
#pragma unroll
                for (int j = 0; j < TN; j++)
                    acc[i][j] += a_[i] * b_[j];
        }
        __syncthreads();
    }

#pragma unroll
    for (int i = 0; i < TM; i++) {
        int row = bm + trow * TM + i;
#pragma unroll
        for (int j = 0; j < TN; j++) {
            int col = bn + tcol * TN + j;
            C[(size_t)row * ldc + col] = acc[i][j] + bias[col];
        }
    }
}

// ---------------- row softmax over N=512 (one block per row) --------------
__global__ void softmax512_kernel(const float* __restrict__ in, float* __restrict__ out)
{
    const int row = blockIdx.x;
    const float* x = in + (size_t)row * 512;
    const int tid = threadIdx.x;  // 256 threads
    __shared__ float red[8];

    float v0 = x[tid], v1 = x[tid + 256];
    float m = fmaxf(v0, v1);
#pragma unroll
    for (int o = 16; o > 0; o >>= 1) m = fmaxf(m, __shfl_xor_sync(0xffffffffu, m, o));
    if ((tid & 31) == 0) red[tid >> 5] = m;
    __syncthreads();
    if (tid == 0) {
        float t = red[0];
#pragma unroll
        for (int i = 1; i < 8; i++) t = fmaxf(t, red[i]);
        red[0] = t;
    }
    __syncthreads();
    m = red[0];
    __syncthreads();

    float e0 = expf(v0 - m), e1 = expf(v1 - m);
    float s = e0 + e1;
#pragma unroll
    for (int o = 16; o > 0; o >>= 1) s += __shfl_xor_sync(0xffffffffu, s, o);
    if ((tid & 31) == 0) red[tid >> 5] = s;
    __syncthreads();
    if (tid == 0) {
        float t = 0.f;
#pragma unroll
        for (int i = 0; i < 8; i++) t += red[i];
        red[0] = t;
    }
    __syncthreads();
    float inv = 1.f / red[0];
    out[(size_t)row * 512 + tid] = e0 * inv;
    out[(size_t)row * 512 + tid + 256] = e1 * inv;
}

// ---- fused attention: scores (bph,bh->bp) + softmax_p + ctx (bp,bph->bh) --
__global__ void attention_kernel(const float* __restrict__ a, float* __restrict__ ctx)
{
    const int b = blockIdx.x;
    const int tid = threadIdx.x;  // 256 threads
    const int lane = tid & 31, warp = tid >> 5;
    __shared__ float sa[HID];
    __shared__ float sw[NP];
    const float* fb = g_feats + (size_t)b * NP * HID;

    sa[tid] = a[(size_t)b * HID + tid];
    sa[tid + 256] = a[(size_t)b * HID + tid + 256];
    __syncthreads();

    // scores: one warp per position, 8 positions per warp
    for (int p = warp; p < NP; p += 8) {
        const float* fr = fb + (size_t)p * HID;
        float s = 0.f;
        for (int e = lane; e < HID; e += 32) s += fr[e] * sa[e];
#pragma unroll
        for (int o = 16; o > 0; o >>= 1) s += __shfl_xor_sync(0xffffffffu, s, o);
        if (lane == 0) sw[p] = s;
    }
    __syncthreads();

    // softmax over 64 positions (warp 0)
    if (tid < 32) {
        float v0 = sw[tid], v1 = sw[tid + 32];
        float m = fmaxf(v0, v1);
#pragma unroll
        for (int o = 16; o > 0; o >>= 1) m = fmaxf(m, __shfl_xor_sync(0xffffffffu, m, o));
        float e0 = expf(v0 - m), e1 = expf(v1 - m);
        float s = e0 + e1;
#pragma unroll
        for (int o = 16; o > 0; o >>= 1) s += __shfl_xor_sync(0xffffffffu, s, o);
        float inv = 1.f / s;
        sw[tid] = e0 * inv;
        sw[tid + 32] = e1 * inv;
    }
    __syncthreads();

    // ctx = sum_p w[p] * feats[b,p,:]
    float acc0 = 0.f, acc1 = 0.f;
#pragma unroll 4
    for (int p = 0; p < NP; p++) {
        float w = sw[p];
        acc0 += w * fb[(size_t)p * HID + tid];
        acc1 += w * fb[(size_t)p * HID + tid + 256];
    }
    ctx[(size_t)b * HID + tid] = acc0;
    ctx[(size_t)b * HID + tid + 256] = acc1;
}

// ---------------- LSTM pointwise ------------------------------------------
__global__ void lstm_kernel()
{
    int idx = blockIdx.x * blockDim.x + threadIdx.x;  // 512*512
    int b = idx >> 9, j = idx & 511;
    const float* gr = g_gates + (size_t)b * 2048;
    float gi = gr[j], gf = gr[512 + j], gg = gr[1024 + j], go = gr[1536 + j];
    float c = g_c[idx];
    float si = 1.f / (1.f + expf(-gi));
    float sf = 1.f / (1.f + expf(-gf));
    float so = 1.f / (1.f + expf(-go));
    float cn = sf * c + si * tanhf(gg);
    g_c[idx] = cn;
    g_h[idx] = so * tanhf(cn);
}

// ---------------- setup kernels -------------------------------------------
__global__ void zero_hc_kernel()
{
    int idx = blockIdx.x * blockDim.x + threadIdx.x;
    g_h[idx] = 0.f;
    g_c[idx] = 0.f;
}

__global__ void build_wg_kernel(const float* __restrict__ Wih, const float* __restrict__ Whh,
                                const float* __restrict__ bih, const float* __restrict__ bhh)
{
    int idx = blockIdx.x * blockDim.x + threadIdx.x;  // 2048*1024
    int n = idx >> 10, k = idx & 1023;
    g_Wg[idx] = (k < 512) ? Wih[(size_t)n * 512 + k] : Whh[(size_t)n * 512 + (k - 512)];
    if (k == 0) g_bg[n] = bih[n] + bhh[n];
}

__global__ void gather_emb_kernel(const int* __restrict__ targets,
                                  const float* __restrict__ table)
{
    int b = blockIdx.x;
    int t = blockIdx.y;
    int id = (t == 0) ? 0 : targets[(size_t)b * TT + (t - 1)];
    const float* src = table + (size_t)id * EMB;
    float* dst = g_emb + ((size_t)t * BATCH + b) * EMB;
    for (int e = threadIdx.x; e < EMB; e += blockDim.x) dst[e] = src[e];
}

// ---------------- launch ----------------------------------------------------
extern "C" void kernel_launch(void* const* d_in, const int* in_sizes, int n_in,
                              void* d_out, int out_size)
{
    const float* features  = (const float*)d_in[0];
    const int*   targets   = (const int*)d_in[1];
    // d_in[2] = max_length (fixed 30, shapes hardcoded)
    const float* Wfc = (const float*)d_in[3];
    const float* bfc = (const float*)d_in[4];
    const float* emb_table = (const float*)d_in[5];
    const float* Wa  = (const float*)d_in[6];
    const float* ba  = (const float*)d_in[7];
    const float* Wc  = (const float*)d_in[8];
    const float* bc  = (const float*)d_in[9];
    const float* Wih = (const float*)d_in[10];
    const float* Whh = (const float*)d_in[11];
    const float* bih = (const float*)d_in[12];
    const float* bhh = (const float*)d_in[13];
    const float* Wo  = (const float*)d_in[14];
    const float* bo  = (const float*)d_in[15];
    float* out = (float*)d_out;

    float *p_feats, *p_emb, *p_h, *p_logits, *p_a, *p_ctx, *p_x, *p_gates, *p_Wg, *p_bg;
    cudaGetSymbolAddress((void**)&p_feats,  g_feats);
    cudaGetSymbolAddress((void**)&p_emb,    g_emb);
    cudaGetSymbolAddress((void**)&p_h,      g_h);
    cudaGetSymbolAddress((void**)&p_logits, g_logits);
    cudaGetSymbolAddress((void**)&p_a,      g_a);
    cudaGetSymbolAddress((void**)&p_ctx,    g_ctx);
    cudaGetSymbolAddress((void**)&p_x,      g_x);
    cudaGetSymbolAddress((void**)&p_gates,  g_gates);
    cudaGetSymbolAddress((void**)&p_Wg,     g_Wg);
    cudaGetSymbolAddress((void**)&p_bg,     g_bg);

    // setup
    zero_hc_kernel<<<(BATCH * HID) / 256, 256>>>();
    build_wg_kernel<<<(2048 * 1024) / 256, 256>>>(Wih, Whh, bih, bhh);
    gather_emb_kernel<<<dim3(BATCH, TT), 128>>>(targets, emb_table);

    // feats = features @ Wfc^T + bfc  : M=32768, N=512, K=512
    gemm_bias_kernel<64, 64, 16, 4, 4>
        <<<dim3(HID / 64, (BATCH * NP) / 64), 256>>>(
            features, CIN, CIN, nullptr, 0, CIN, Wfc, bfc, p_feats, HID);

    for (int t = 0; t < TT; t++) {
        const float* emb_t = p_emb + (size_t)t * BATCH * EMB;

        // logits = [h, emb] @ Wa^T + ba : M=512, N=512, K=1024
        gemm_bias_kernel<64, 32, 16, 4, 4>
            <<<dim3(HID / 32, BATCH / 64), 128>>>(
                p_h, HID, HID, emb_t, EMB, HID + EMB, Wa, ba, p_logits, HID);

        softmax512_kernel<<<BATCH, 256>>>(p_logits, p_a);
        attention_kernel<<<BATCH, 256>>>(p_a, p_ctx);

        // x = [emb, ctx] @ Wc^T + bc : M=512, N=512, K=1024
        gemm_bias_kernel<64, 32, 16, 4, 4>
            <<<dim3(HID / 32, BATCH / 64), 128>>>(
                emb_t, EMB, EMB, p_ctx, HID, EMB + HID, Wc, bc, p_x, HID);

        // gates = [x, h] @ [Wih|Whh]^T + (bih+bhh) : M=512, N=2048, K=1024
        gemm_bias_kernel<64, 64, 16, 4, 4>
            <<<dim3((4 * HID) / 64, BATCH / 64), 256>>>(
                p_x, HID, HID, p_h, HID, HID + HID, p_Wg, p_bg, p_gates, 4 * HID);

        lstm_kernel<<<(BATCH * HID) / 256, 256>>>();

        // out[:, t, :] = h @ Wo^T + bo : M=512, N=96, K=512
        gemm_bias_kernel<64, 32, 16, 4, 4>
            <<<dim3(NCLS / 32, BATCH / 64), 128>>>(
                p_h, HID, HID, nullptr, 0, HID, Wo, bo, out + (size_t)t * NCLS, TT * NCLS);
    }
}

// round 2
// speedup vs baseline: 1.2824x; 1.2824x over previous
#include <cuda_runtime.h>
#include <math.h>
#include <stdint.h>

#define BATCH 512
#define NP    64
#define CIN   512
#define HID   512
#define EMB   512
#define NCLS  96
#define TT    30

// ---------------- scratch (device globals; no allocations) ----------------
__device__ float g_feats[(size_t)BATCH * NP * HID];   // 64 MB, L2-resident
__device__ float g_emb[(size_t)TT * BATCH * EMB];     // 31.5 MB
__device__ float g_h[BATCH * HID];
__device__ float g_c[BATCH * HID];
__device__ float g_logits[BATCH * HID];
__device__ float g_ctx[BATCH * HID];
__device__ float g_x[BATCH * HID];
__device__ float g_gates[BATCH * 4 * HID];
__device__ float g_Wg[(size_t)4 * HID * (HID + HID)]; // [2048,1024] = [Wih|Whh]
__device__ float g_bg[4 * HID];

__device__ __forceinline__ uint32_t f2tf32(float f) {
    uint32_t r;
    asm("cvt.rna.tf32.f32 %0, %1;" : "=r"(r) : "f"(f));
    return r;
}

// ------------- TF32 tensor-core GEMM: C = A @ B^T + bias ------------------
// A logically [M,K], split along K: cols [0,K1) from A1 (row stride lda1),
// cols [K1,K) from A2 (row stride lda2). B is [N,K] row-major.
// mma.sync.aligned.m16n8k8.row.col.f32.tf32.tf32.f32
template <int BM, int BN, int WARPS_M, int WARPS_N>
__global__ void __launch_bounds__(WARPS_M * WARPS_N * 32)
gemm_tf32_kernel(const float* __restrict__ A1, int lda1, int K1,
                 const float* __restrict__ A2, int lda2,
                 int K,
                 const float* __restrict__ B,
                 const float* __restrict__ bias,
                 float* __restrict__ C, int ldc)
{
    constexpr int BK = 32;
    constexpr int THREADS = WARPS_M * WARPS_N * 32;
    constexpr int WM = BM / WARPS_M;   // 32
    constexpr int WN = BN / WARPS_N;   // 32 or 16
    constexpr int M_SUB = WM / 16;     // 2
    constexpr int N_SUB = WN / 8;      // 4 or 2
    constexpr int PAD = 4;

    __shared__ uint32_t As[BM][BK + PAD];
    __shared__ uint32_t Bs[BN][BK + PAD];

    const int bm = blockIdx.y * BM;
    const int bn = blockIdx.x * BN;
    const int tid = threadIdx.x;
    const int wid = tid >> 5;
    const int lane = tid & 31;
    const int gid = lane >> 2;   // 0..7
    const int tig = lane & 3;    // 0..3
    const int warpM = wid % WARPS_M;
    const int warpN = wid / WARPS_M;

    float acc[M_SUB][N_SUB][4];
#pragma unroll
    for (int i = 0; i < M_SUB; i++)
#pragma unroll
        for (int j = 0; j < N_SUB; j++)
#pragma unroll
            for (int q = 0; q < 4; q++) acc[i][j][q] = 0.f;

    for (int k0 = 0; k0 < K; k0 += BK) {
        const float* Ap; int lda, kc;
        if (k0 < K1) { Ap = A1; lda = lda1; kc = k0; }
        else         { Ap = A2; lda = lda2; kc = k0 - K1; }

#pragma unroll
        for (int i = 0; i < (BM * BK / 4) / THREADS; i++) {
            int idx = tid + i * THREADS;
            int r = idx >> 3, c4 = idx & 7;
            float4 v = *(const float4*)(Ap + (size_t)(bm + r) * lda + kc + c4 * 4);
            uint4 u = { f2tf32(v.x), f2tf32(v.y), f2tf32(v.z), f2tf32(v.w) };
            *(uint4*)&As[r][c4 * 4] = u;
        }
#pragma unroll
        for (int i = 0; i < (BN * BK / 4) / THREADS; i++) {
            int idx = tid + i * THREADS;
            int r = idx >> 3, c4 = idx & 7;
            float4 v = *(const float4*)(B + (size_t)(bn + r) * K + k0 + c4 * 4);
            uint4 u = { f2tf32(v.x), f2tf32(v.y), f2tf32(v.z), f2tf32(v.w) };
            *(uint4*)&Bs[r][c4 * 4] = u;
        }
        __syncthreads();

#pragma unroll
        for (int ks = 0; ks < BK / 8; ks++) {
            const int kb = ks * 8;
            uint32_t afr[M_SUB][4];
#pragma unroll
            for (int mt = 0; mt < M_SUB; mt++) {
                int r0 = warpM * WM + mt * 16 + gid;
                afr[mt][0] = As[r0][kb + tig];
                afr[mt][1] = As[r0 + 8][kb + tig];
                afr[mt][2] = As[r0][kb + tig + 4];
                afr[mt][3] = As[r0 + 8][kb + tig + 4];
            }
#pragma unroll
            for (int nt = 0; nt < N_SUB; nt++) {
                int c0 = warpN * WN + nt * 8 + gid;
                uint32_t b0 = Bs[c0][kb + tig];
                uint32_t b1 = Bs[c0][kb + tig + 4];
#pragma unroll
                for (int mt = 0; mt < M_SUB; mt++) {
                    asm volatile(
                        "mma.sync.aligned.m16n8k8.row.col.f32.tf32.tf32.f32 "
                        "{%0,%1,%2,%3}, {%4,%5,%6,%7}, {%8,%9}, {%0,%1,%2,%3};"
                        : "+f"(acc[mt][nt][0]), "+f"(acc[mt][nt][1]),
                          "+f"(acc[mt][nt][2]), "+f"(acc[mt][nt][3])
                        : "r"(afr[mt][0]), "r"(afr[mt][1]),
                          "r"(afr[mt][2]), "r"(afr[mt][3]),
                          "r"(b0), "r"(b1));
                }
            }
        }
        __syncthreads();
    }

#pragma unroll
    for (int mt = 0; mt < M_SUB; mt++) {
#pragma unroll
        for (int nt = 0; nt < N_SUB; nt++) {
            int row0 = bm + warpM * WM + mt * 16 + gid;
            int col  = bn + warpN * WN + nt * 8 + 2 * tig;
            float2 bv = *(const float2*)(bias + col);
            float2 v0 = { acc[mt][nt][0] + bv.x, acc[mt][nt][1] + bv.y };
            float2 v1 = { acc[mt][nt][2] + bv.x, acc[mt][nt][3] + bv.y };
            *(float2*)(C + (size_t)row0 * ldc + col) = v0;
            *(float2*)(C + (size_t)(row0 + 8) * ldc + col) = v1;
        }
    }
}

// ---- fused: softmax(logits) -> scores -> softmax_p -> ctx  ----------------
__global__ void attention_kernel(const float* __restrict__ logits, float* __restrict__ ctx)
{
    const int b = blockIdx.x;
    const int tid = threadIdx.x;  // 256 threads
    const int lane = tid & 31, warp = tid >> 5;
    __shared__ float sa[HID];
    __shared__ float sw[NP];
    __shared__ float red[8];
    const float* fb = g_feats + (size_t)b * NP * HID;

    // softmax over hidden dim of logits row
    const float* x = logits + (size_t)b * HID;
    float v0 = x[tid], v1 = x[tid + 256];
    float m = fmaxf(v0, v1);
#pragma unroll
    for (int o = 16; o > 0; o >>= 1) m = fmaxf(m, __shfl_xor_sync(0xffffffffu, m, o));
    if (lane == 0) red[warp] = m;
    __syncthreads();
    if (tid == 0) {
        float t = red[0];
#pragma unroll
        for (int i = 1; i < 8; i++) t = fmaxf(t, red[i]);
        red[0] = t;
    }
    __syncthreads();
    m = red[0];
    __syncthreads();
    float e0 = expf(v0 - m), e1 = expf(v1 - m);
    float s = e0 + e1;
#pragma unroll
    for (int o = 16; o > 0; o >>= 1) s += __shfl_xor_sync(0xffffffffu, s, o);
    if (lane == 0) red[warp] = s;
    __syncthreads();
    if (tid == 0) {
        float t = 0.f;
#pragma unroll
        for (int i = 0; i < 8; i++) t += red[i];
        red[0] = t;
    }
    __syncthreads();
    float inv = 1.f / red[0];
    sa[tid] = e0 * inv;
    sa[tid + 256] = e1 * inv;
    __syncthreads();

    // scores: one warp per position, 8 positions per warp
    for (int p = warp; p < NP; p += 8) {
        const float* fr = fb + (size_t)p * HID;
        float sc = 0.f;
        for (int e = lane; e < HID; e += 32) sc += fr[e] * sa[e];
#pragma unroll
        for (int o = 16; o > 0; o >>= 1) sc += __shfl_xor_sync(0xffffffffu, sc, o);
        if (lane == 0) sw[p] = sc;
    }
    __syncthreads();

    // softmax over 64 positions (warp 0)
    if (tid < 32) {
        float w0 = sw[tid], w1 = sw[tid + 32];
        float mm = fmaxf(w0, w1);
#pragma unroll
        for (int o = 16; o > 0; o >>= 1) mm = fmaxf(mm, __shfl_xor_sync(0xffffffffu, mm, o));
        float f0 = expf(w0 - mm), f1 = expf(w1 - mm);
        float ss = f0 + f1;
#pragma unroll
        for (int o = 16; o > 0; o >>= 1) ss += __shfl_xor_sync(0xffffffffu, ss, o);
        float iv = 1.f / ss;
        sw[tid] = f0 * iv;
        sw[tid + 32] = f1 * iv;
    }
    __syncthreads();

    // ctx = sum_p w[p] * feats[b,p,:]
    float acc0 = 0.f, acc1 = 0.f;
#pragma unroll 4
    for (int p = 0; p < NP; p++) {
        float w = sw[p];
        acc0 += w * fb[(size_t)p * HID + tid];
        acc1 += w * fb[(size_t)p * HID + tid + 256];
    }
    ctx[(size_t)b * HID + tid] = acc0;
    ctx[(size_t)b * HID + tid + 256] = acc1;
}

// ---------------- LSTM pointwise ------------------------------------------
__global__ void lstm_kernel()
{
    int idx = blockIdx.x * blockDim.x + threadIdx.x;  // 512*512
    int b = idx >> 9, j = idx & 511;
    const float* gr = g_gates + (size_t)b * 2048;
    float gi = gr[j], gf = gr[512 + j], gg = gr[1024 + j], go = gr[1536 + j];
    float c = g_c[idx];
    float si = 1.f / (1.f + expf(-gi));
    float sf = 1.f / (1.f + expf(-gf));
    float so = 1.f / (1.f + expf(-go));
    float cn = sf * c + si * tanhf(gg);
    g_c[idx] = cn;
    g_h[idx] = so * tanhf(cn);
}

// ---------------- setup kernels -------------------------------------------
__global__ void zero_hc_kernel()
{
    int idx = blockIdx.x * blockDim.x + threadIdx.x;
    g_h[idx] = 0.f;
    g_c[idx] = 0.f;
}

__global__ void build_wg_kernel(const float* __restrict__ Wih, const float* __restrict__ Whh,
                                const float* __restrict__ bih, const float* __restrict__ bhh)
{
    int idx = blockIdx.x * blockDim.x + threadIdx.x;  // 2048*1024
    int n = idx >> 10, k = idx & 1023;
    g_Wg[idx] = (k < 512) ? Wih[(size_t)n * 512 + k] : Whh[(size_t)n * 512 + (k - 512)];
    if (k == 0) g_bg[n] = bih[n] + bhh[n];
}

__global__ void gather_emb_kernel(const int* __restrict__ targets,
                                  const float* __restrict__ table)
{
    int b = blockIdx.x;
    int t = blockIdx.y;
    int id = (t == 0) ? 0 : targets[(size_t)b * TT + (t - 1)];
    const float* src = table + (size_t)id * EMB;
    float* dst = g_emb + ((size_t)t * BATCH + b) * EMB;
    for (int e = threadIdx.x; e < EMB; e += blockDim.x) dst[e] = src[e];
}

// ---------------- launch ----------------------------------------------------
extern "C" void kernel_launch(void* const* d_in, const int* in_sizes, int n_in,
                              void* d_out, int out_size)
{
    const float* features  = (const float*)d_in[0];
    const int*   targets   = (const int*)d_in[1];
    const float* Wfc = (const float*)d_in[3];
    const float* bfc = (const float*)d_in[4];
    const float* emb_table = (const float*)d_in[5];
    const float* Wa  = (const float*)d_in[6];
    const float* ba  = (const float*)d_in[7];
    const float* Wc  = (const float*)d_in[8];
    const float* bc  = (const float*)d_in[9];
    const float* Wih = (const float*)d_in[10];
    const float* Whh = (const float*)d_in[11];
    const float* bih = (const float*)d_in[12];
    const float* bhh = (const float*)d_in[13];
    const float* Wo  = (const float*)d_in[14];
    const float* bo  = (const float*)d_in[15];
    float* out = (float*)d_out;

    float *p_feats, *p_emb, *p_h, *p_logits, *p_ctx, *p_x, *p_gates, *p_Wg, *p_bg;
    cudaGetSymbolAddress((void**)&p_feats,  g_feats);
    cudaGetSymbolAddress((void**)&p_emb,    g_emb);
    cudaGetSymbolAddress((void**)&p_h,      g_h);
    cudaGetSymbolAddress((void**)&p_logits, g_logits);
    cudaGetSymbolAddress((void**)&p_ctx,    g_ctx);
    cudaGetSymbolAddress((void**)&p_x,      g_x);
    cudaGetSymbolAddress((void**)&p_gates,  g_gates);
    cudaGetSymbolAddress((void**)&p_Wg,     g_Wg);
    cudaGetSymbolAddress((void**)&p_bg,     g_bg);

    // setup
    zero_hc_kernel<<<(BATCH * HID) / 256, 256>>>();
    build_wg_kernel<<<(2048 * 1024) / 256, 256>>>(Wih, Whh, bih, bhh);
    gather_emb_kernel<<<dim3(BATCH, TT), 128>>>(targets, emb_table);

    // feats = features @ Wfc^T + bfc : M=32768, N=512, K=512
    gemm_tf32_kernel<128, 64, 4, 2>
        <<<dim3(HID / 64, (BATCH * NP) / 128), 256>>>(
            features, CIN, CIN, nullptr, 0, CIN, Wfc, bfc, p_feats, HID);

    for (int t = 0; t < TT; t++) {
        const float* emb_t = p_emb + (size_t)t * BATCH * EMB;

        // logits = [h, emb] @ Wa^T + ba : M=512, N=512, K=1024
        gemm_tf32_kernel<64, 64, 2, 2>
            <<<dim3(HID / 64, BATCH / 64), 128>>>(
                p_h, HID, HID, emb_t, EMB, HID + EMB, Wa, ba, p_logits, HID);

        attention_kernel<<<BATCH, 256>>>(p_logits, p_ctx);

        // x = [emb, ctx] @ Wc^T + bc : M=512, N=512, K=1024
        gemm_tf32_kernel<64, 64, 2, 2>
            <<<dim3(HID / 64, BATCH / 64), 128>>>(
                emb_t, EMB, EMB, p_ctx, HID, EMB + HID, Wc, bc, p_x, HID);

        // gates = [x, h] @ [Wih|Whh]^T + (bih+bhh) : M=512, N=2048, K=1024
        gemm_tf32_kernel<128, 64, 4, 2>
            <<<dim3((4 * HID) / 64, BATCH / 128), 256>>>(
                p_x, HID, HID, p_h, HID, HID + HID, p_Wg, p_bg, p_gates, 4 * HID);

        lstm_kernel<<<(BATCH * HID) / 256, 256>>>();

        // out[:, t, :] = h @ Wo^T + bo : M=512, N=96, K=512
        gemm_tf32_kernel<64, 32, 2, 2>
            <<<dim3(NCLS / 32, BATCH / 64), 128>>>(
                p_h, HID, HID, nullptr, 0, HID, Wo, bo, out + (size_t)t * NCLS, TT * NCLS);
    }
}

// round 3
// speedup vs baseline: 3.0751x; 2.3980x over previous
#include <cuda_runtime.h>
#include <math.h>
#include <stdint.h>

#define BATCH 512
#define NP    64
#define CIN   512
#define HID   512
#define EMB   512
#define NCLS  96
#define TT    30

// ---------------- scratch (device globals; no allocations) ----------------
__device__ float g_feats[(size_t)BATCH * NP * HID];   // 64 MB, L2-resident
__device__ float g_emb[(size_t)TT * BATCH * EMB];     // 31.5 MB
__device__ float g_lpre[(size_t)TT * BATCH * HID];    // emb @ WaE^T + ba
__device__ float g_xpre[(size_t)TT * BATCH * HID];    // emb @ WcE^T + bc
__device__ float g_hist[(size_t)TT * BATCH * HID];    // h_t history
__device__ float g_hbuf[2][BATCH * HID];              // ping-pong h
__device__ float g_c[BATCH * HID];
__device__ float g_logits[BATCH * HID];
__device__ float g_ctx[BATCH * HID];
__device__ float g_x[BATCH * HID];
__device__ float g_Wg[(size_t)4 * HID * (HID + HID)]; // gate-interleaved [2048,1024]
__device__ float g_bg[4 * HID];

__device__ __forceinline__ uint32_t f2tf32(float f) {
    uint32_t r;
    asm("cvt.rna.tf32.f32 %0, %1;" : "=r"(r) : "f"(f));
    return r;
}

// ------------- TF32 tensor-core GEMM: C = A @ B^T (+bias)(+addend) --------
// A logically [M,K] split along K: cols [0,K1) from A1 (stride lda1),
// cols [K1,K) from A2 (stride lda2). B rows: B + n*ldb + boff.
// MODE 0: C[row*ldc+col] = acc + bias? + addend?
// MODE 1: fused LSTM epilogue (gate-interleaved cols); writes g_c, h_out, g_hist
// MODE 2: permuted out write: row r -> (b*TT + t), b=r&511, t=r>>9
template <int BM, int BN, int WARPS_M, int WARPS_N, int MODE>
__global__ void __launch_bounds__(WARPS_M * WARPS_N * 32)
gemm_tf32(const float* __restrict__ A1, int lda1, int K1,
          const float* __restrict__ A2, int lda2, int K,
          const float* __restrict__ B, int ldb, int boff,
          const float* __restrict__ bias, const float* __restrict__ addend,
          float* __restrict__ C, int ldc,
          float* __restrict__ h_out, int t)
{
    constexpr int BK = 32;
    constexpr int THREADS = WARPS_M * WARPS_N * 32;
    constexpr int WM = BM / WARPS_M;
    constexpr int WN = BN / WARPS_N;
    constexpr int M_SUB = WM / 16;
    constexpr int N_SUB = WN / 8;
    constexpr int PAD = 4;
    constexpr int AV = (BM * BK) / (THREADS * 4);
    constexpr int BV = (BN * BK) / (THREADS * 4);
    constexpr int ASZ = BM * (BK + PAD);
    constexpr int BSZ = BN * (BK + PAD);
    constexpr int CSZ = (MODE == 1) ? BM * (BN + PAD) : 0;
    constexpr int SHN = (ASZ + BSZ > CSZ) ? (ASZ + BSZ) : CSZ;

    __shared__ uint32_t sh[SHN];
    uint32_t (*As)[BK + PAD] = (uint32_t(*)[BK + PAD])sh;
    uint32_t (*Bs)[BK + PAD] = (uint32_t(*)[BK + PAD])(sh + ASZ);

    const int bm = blockIdx.y * BM;
    const int bn = blockIdx.x * BN;
    const int tid = threadIdx.x;
    const int wid = tid >> 5;
    const int lane = tid & 31;
    const int gid = lane >> 2;
    const int tig = lane & 3;
    const int warpM = wid % WARPS_M;
    const int warpN = wid / WARPS_M;

    float acc[M_SUB][N_SUB][4];
#pragma unroll
    for (int i = 0; i < M_SUB; i++)
#pragma unroll
        for (int j = 0; j < N_SUB; j++)
#pragma unroll
            for (int q = 0; q < 4; q++) acc[i][j][q] = 0.f;

    float4 ra[AV], rb[BV];

    auto loadA = [&](int k0) {
        const float* Ap; int lda, kc;
        if (k0 < K1) { Ap = A1; lda = lda1; kc = k0; }
        else         { Ap = A2; lda = lda2; kc = k0 - K1; }
#pragma unroll
        for (int i = 0; i < AV; i++) {
            int idx = tid + i * THREADS;
            int r = idx >> 3, c4 = idx & 7;
            ra[i] = *(const float4*)(Ap + (size_t)(bm + r) * lda + kc + c4 * 4);
        }
    };
    auto loadB = [&](int k0) {
#pragma unroll
        for (int i = 0; i < BV; i++) {
            int idx = tid + i * THREADS;
            int r = idx >> 3, c4 = idx & 7;
            rb[i] = *(const float4*)(B + (size_t)(bn + r) * ldb + boff + k0 + c4 * 4);
        }
    };
    auto stsAB = [&]() {
#pragma unroll
        for (int i = 0; i < AV; i++) {
            int idx = tid + i * THREADS;
            int r = idx >> 3, c4 = idx & 7;
            uint4 u = { f2tf32(ra[i].x), f2tf32(ra[i].y), f2tf32(ra[i].z), f2tf32(ra[i].w) };
            *(uint4*)&As[r][c4 * 4] = u;
        }
#pragma unroll
        for (int i = 0; i < BV; i++) {
            int idx = tid + i * THREADS;
            int r = idx >> 3, c4 = idx & 7;
            uint4 u = { f2tf32(rb[i].x), f2tf32(rb[i].y), f2tf32(rb[i].z), f2tf32(rb[i].w) };
            *(uint4*)&Bs[r][c4 * 4] = u;
        }
    };

    loadA(0); loadB(0);
    stsAB();
    __syncthreads();

    for (int k0 = 0; k0 < K; k0 += BK) {
        const bool more = (k0 + BK < K);
        if (more) { loadA(k0 + BK); loadB(k0 + BK); }

#pragma unroll
        for (int ks = 0; ks < BK / 8; ks++) {
            const int kb = ks * 8;
            uint32_t afr[M_SUB][4];
#pragma unroll
            for (int mt = 0; mt < M_SUB; mt++) {
                int r0 = warpM * WM + mt * 16 + gid;
                afr[mt][0] = As[r0][kb + tig];
                afr[mt][1] = As[r0 + 8][kb + tig];
                afr[mt][2] = As[r0][kb + tig + 4];
                afr[mt][3] = As[r0 + 8][kb + tig + 4];
            }
#pragma unroll
            for (int nt = 0; nt < N_SUB; nt++) {
                int c0 = warpN * WN + nt * 8 + gid;
                uint32_t b0 = Bs[c0][kb + tig];
                uint32_t b1 = Bs[c0][kb + tig + 4];
#pragma unroll
                for (int mt = 0; mt < M_SUB; mt++) {
                    asm volatile(
                        "mma.sync.aligned.m16n8k8.row.col.f32.tf32.tf32.f32 "
                        "{%0,%1,%2,%3}, {%4,%5,%6,%7}, {%8,%9}, {%0,%1,%2,%3};"
                        : "+f"(acc[mt][nt][0]), "+f"(acc[mt][nt][1]),
                          "+f"(acc[mt][nt][2]), "+f"(acc[mt][nt][3])
                        : "r"(afr[mt][0]), "r"(afr[mt][1]),
                          "r"(afr[mt][2]), "r"(afr[mt][3]),
                          "r"(b0), "r"(b1));
                }
            }
        }
        __syncthreads();
        if (more) {
            stsAB();
            __syncthreads();
        }
    }

    if constexpr (MODE == 0) {
#pragma unroll
        for (int mt = 0; mt < M_SUB; mt++) {
#pragma unroll
            for (int nt = 0; nt < N_SUB; nt++) {
                int row0 = bm + warpM * WM + mt * 16 + gid;
                int col  = bn + warpN * WN + nt * 8 + 2 * tig;
                float bx = 0.f, by = 0.f;
                if (bias) { float2 bv = *(const float2*)(bias + col); bx = bv.x; by = bv.y; }
                float a0x = 0.f, a0y = 0.f, a1x = 0.f, a1y = 0.f;
                if (addend) {
                    float2 v = *(const float2*)(addend + (size_t)row0 * ldc + col);
                    a0x = v.x; a0y = v.y;
                    float2 w = *(const float2*)(addend + (size_t)(row0 + 8) * ldc + col);
                    a1x = w.x; a1y = w.y;
                }
                float2 v0 = { acc[mt][nt][0] + bx + a0x, acc[mt][nt][1] + by + a0y };
                float2 v1 = { acc[mt][nt][2] + bx + a1x, acc[mt][nt][3] + by + a1y };
                *(float2*)(C + (size_t)row0 * ldc + col) = v0;
                *(float2*)(C + (size_t)(row0 + 8) * ldc + col) = v1;
            }
        }
    } else if constexpr (MODE == 2) {
#pragma unroll
        for (int mt = 0; mt < M_SUB; mt++) {
#pragma unroll
            for (int nt = 0; nt < N_SUB; nt++) {
                int row0 = bm + warpM * WM + mt * 16 + gid;
                int col  = bn + warpN * WN + nt * 8 + 2 * tig;
                float2 bv = *(const float2*)(bias + col);
#pragma unroll
                for (int rr = 0; rr < 2; rr++) {
                    int r = row0 + rr * 8;
                    int tt = r >> 9, b = r & 511;
                    float2 v = { acc[mt][nt][rr * 2 + 0] + bv.x,
                                 acc[mt][nt][rr * 2 + 1] + bv.y };
                    *(float2*)(C + ((size_t)b * TT + tt) * NCLS + col) = v;
                }
            }
        }
    } else {  // MODE == 1: fused LSTM
        float* Cs = (float*)sh;
        __syncthreads();  // ensure As/Bs reads done before overwrite
#pragma unroll
        for (int mt = 0; mt < M_SUB; mt++) {
#pragma unroll
            for (int nt = 0; nt < N_SUB; nt++) {
                int rl = warpM * WM + mt * 16 + gid;
                int cl = warpN * WN + nt * 8 + 2 * tig;
                float b0 = g_bg[bn + cl], b1 = g_bg[bn + cl + 1];
                Cs[rl * (BN + PAD) + cl]           = acc[mt][nt][0] + b0;
                Cs[rl * (BN + PAD) + cl + 1]       = acc[mt][nt][1] + b1;
                Cs[(rl + 8) * (BN + PAD) + cl]     = acc[mt][nt][2] + b0;
                Cs[(rl + 8) * (BN + PAD) + cl + 1] = acc[mt][nt][3] + b1;
            }
        }
        __syncthreads();
        constexpr int UNITS = BN / 4;
        for (int it = tid; it < BM * UNITS; it += THREADS) {
            int r = it / UNITS, u = it % UNITS;
            float gi = Cs[r * (BN + PAD) + 4 * u + 0];
            float gf = Cs[r * (BN + PAD) + 4 * u + 1];
            float gg = Cs[r * (BN + PAD) + 4 * u + 2];
            float go = Cs[r * (BN + PAD) + 4 * u + 3];
            int b = bm + r;
            int j = (bn >> 2) + u;
            int idx = b * HID + j;
            float c = g_c[idx];
            float si = 1.f / (1.f + expf(-gi));
            float sf = 1.f / (1.f + expf(-gf));
            float so = 1.f / (1.f + expf(-go));
            float cn = sf * c + si * tanhf(gg);
            g_c[idx] = cn;
            float hn = so * tanhf(cn);
            h_out[idx] = hn;
            g_hist[(size_t)t * BATCH * HID + idx] = hn;
        }
    }
}

// ---- fused: softmax(logits) -> scores -> softmax_p -> ctx  ----------------
__global__ void attention_kernel(const float* __restrict__ logits, float* __restrict__ ctx)
{
    const int b = blockIdx.x;
    const int tid = threadIdx.x;  // 256
    const int lane = tid & 31, warp = tid >> 5;
    __shared__ float sa[HID];
    __shared__ float sw[NP];
    __shared__ float red[8];
    const float* fb = g_feats + (size_t)b * NP * HID;

    const float* x = logits + (size_t)b * HID;
    float v0 = x[tid], v1 = x[tid + 256];
    float m = fmaxf(v0, v1);
#pragma unroll
    for (int o = 16; o > 0; o >>= 1) m = fmaxf(m, __shfl_xor_sync(0xffffffffu, m, o));
    if (lane == 0) red[warp] = m;
    __syncthreads();
    if (tid == 0) {
        float t = red[0];
#pragma unroll
        for (int i = 1; i < 8; i++) t = fmaxf(t, red[i]);
        red[0] = t;
    }
    __syncthreads();
    m = red[0];
    __syncthreads();
    float e0 = expf(v0 - m), e1 = expf(v1 - m);
    float s = e0 + e1;
#pragma unroll
    for (int o = 16; o > 0; o >>= 1) s += __shfl_xor_sync(0xffffffffu, s, o);
    if (lane == 0) red[warp] = s;
    __syncthreads();
    if (tid == 0) {
        float t = 0.f;
#pragma unroll
        for (int i = 0; i < 8; i++) t += red[i];
        red[0] = t;
    }
    __syncthreads();
    float inv = 1.f / red[0];
    sa[tid] = e0 * inv;
    sa[tid + 256] = e1 * inv;
    __syncthreads();

    for (int p = warp; p < NP; p += 8) {
        const float* fr = fb + (size_t)p * HID;
        float sc = 0.f;
        for (int e = lane; e < HID; e += 32) sc += fr[e] * sa[e];
#pragma unroll
        for (int o = 16; o > 0; o >>= 1) sc += __shfl_xor_sync(0xffffffffu, sc, o);
        if (lane == 0) sw[p] = sc;
    }
    __syncthreads();

    if (tid < 32) {
        float w0 = sw[tid], w1 = sw[tid + 32];
        float mm = fmaxf(w0, w1);
#pragma unroll
        for (int o = 16; o > 0; o >>= 1) mm = fmaxf(mm, __shfl_xor_sync(0xffffffffu, mm, o));
        float f0 = expf(w0 - mm), f1 = expf(w1 - mm);
        float ss = f0 + f1;
#pragma unroll
        for (int o = 16; o > 0; o >>= 1) ss += __shfl_xor_sync(0xffffffffu, ss, o);
        float iv = 1.f / ss;
        sw[tid] = f0 * iv;
        sw[tid + 32] = f1 * iv;
    }
    __syncthreads();

    float acc0 = 0.f, acc1 = 0.f;
#pragma unroll 4
    for (int p = 0; p < NP; p++) {
        float w = sw[p];
        acc0 += w * fb[(size_t)p * HID + tid];
        acc1 += w * fb[(size_t)p * HID + tid + 256];
    }
    ctx[(size_t)b * HID + tid] = acc0;
    ctx[(size_t)b * HID + tid + 256] = acc1;
}

// ---------------- setup kernels -------------------------------------------
__global__ void zero_hc_kernel()
{
    int idx = blockIdx.x * blockDim.x + threadIdx.x;
    g_hbuf[0][idx] = 0.f;
    g_c[idx] = 0.f;
}

// gate-interleaved Wg: row (4j+gi) = original row (gi*512 + j); cols [Wih|Whh]
__global__ void build_wg_kernel(const float* __restrict__ Wih, const float* __restrict__ Whh,
                                const float* __restrict__ bih, const float* __restrict__ bhh)
{
    int idx = blockIdx.x * blockDim.x + threadIdx.x;  // 2048*1024
    int rn = idx >> 10, k = idx & 1023;
    int j = rn >> 2, gi = rn & 3;
    int orig = gi * 512 + j;
    g_Wg[idx] = (k < 512) ? Wih[(size_t)orig * 512 + k] : Whh[(size_t)orig * 512 + (k - 512)];
    if (k == 0) g_bg[rn] = bih[orig] + bhh[orig];
}

__global__ void gather_emb_kernel(const int* __restrict__ targets,
                                  const float* __restrict__ table)
{
    int b = blockIdx.x;
    int t = blockIdx.y;
    int id = (t == 0) ? 0 : targets[(size_t)b * TT + (t - 1)];
    const float* src = table + (size_t)id * EMB;
    float* dst = g_emb + ((size_t)t * BATCH + b) * EMB;
    for (int e = threadIdx.x; e < EMB; e += blockDim.x) dst[e] = src[e];
}

// ---------------- launch ----------------------------------------------------
extern "C" void kernel_launch(void* const* d_in, const int* in_sizes, int n_in,
                              void* d_out, int out_size)
{
    const float* features  = (const float*)d_in[0];
    const int*   targets   = (const int*)d_in[1];
    const float* Wfc = (const float*)d_in[3];
    const float* bfc = (const float*)d_in[4];
    const float* emb_table = (const float*)d_in[5];
    const float* Wa  = (const float*)d_in[6];
    const float* ba  = (const float*)d_in[7];
    const float* Wc  = (const float*)d_in[8];
    const float* bc  = (const float*)d_in[9];
    const float* Wih = (const float*)d_in[10];
    const float* Whh = (const float*)d_in[11];
    const float* bih = (const float*)d_in[12];
    const float* bhh = (const float*)d_in[13];
    const float* Wo  = (const float*)d_in[14];
    const float* bo  = (const float*)d_in[15];
    float* out = (float*)d_out;

    float *p_feats, *p_emb, *p_lpre, *p_xpre, *p_hist, *p_hbuf, *p_logits, *p_ctx, *p_x, *p_Wg;
    cudaGetSymbolAddress((void**)&p_feats,  g_feats);
    cudaGetSymbolAddress((void**)&p_emb,    g_emb);
    cudaGetSymbolAddress((void**)&p_lpre,   g_lpre);
    cudaGetSymbolAddress((void**)&p_xpre,   g_xpre);
    cudaGetSymbolAddress((void**)&p_hist,   g_hist);
    cudaGetSymbolAddress((void**)&p_hbuf,   g_hbuf);
    cudaGetSymbolAddress((void**)&p_logits, g_logits);
    cudaGetSymbolAddress((void**)&p_ctx,    g_ctx);
    cudaGetSymbolAddress((void**)&p_x,      g_x);
    cudaGetSymbolAddress((void**)&p_Wg,     g_Wg);

    // setup
    zero_hc_kernel<<<(BATCH * HID) / 256, 256>>>();
    build_wg_kernel<<<(2048 * 1024) / 256, 256>>>(Wih, Whh, bih, bhh);
    gather_emb_kernel<<<dim3(BATCH, TT), 128>>>(targets, emb_table);

    // feats = features @ Wfc^T + bfc : M=32768, N=512, K=512
    gemm_tf32<128, 64, 4, 2, 0><<<dim3(HID / 64, (BATCH * NP) / 128), 256>>>(
        features, CIN, CIN, nullptr, 0, CIN,
        Wfc, CIN, 0, bfc, nullptr, p_feats, HID, nullptr, 0);

    // lpre = emb @ Wa[:,512:]^T + ba : M=15360, N=512, K=512
    gemm_tf32<128, 64, 4, 2, 0><<<dim3(HID / 64, (TT * BATCH) / 128), 256>>>(
        p_emb, EMB, EMB, nullptr, 0, EMB,
        Wa, HID + EMB, 512, ba, nullptr, p_lpre, HID, nullptr, 0);

    // xpre = emb @ Wc[:,:512]^T + bc : M=15360, N=512, K=512
    gemm_tf32<128, 64, 4, 2, 0><<<dim3(HID / 64, (TT * BATCH) / 128), 256>>>(
        p_emb, EMB, EMB, nullptr, 0, EMB,
        Wc, EMB + HID, 0, bc, nullptr, p_xpre, HID, nullptr, 0);

    for (int t = 0; t < TT; t++) {
        float* hr = p_hbuf + (t & 1) * BATCH * HID;
        float* hw = p_hbuf + ((t + 1) & 1) * BATCH * HID;

        // logits = h @ Wa[:,:512]^T + lpre[t] : M=512, N=512, K=512
        gemm_tf32<64, 32, 2, 2, 0><<<dim3(HID / 32, BATCH / 64), 128>>>(
            hr, HID, HID, nullptr, 0, HID,
            Wa, HID + EMB, 0, nullptr, p_lpre + (size_t)t * BATCH * HID,
            p_logits, HID, nullptr, 0);

        attention_kernel<<<BATCH, 256>>>(p_logits, p_ctx);

        // x = ctx @ Wc[:,512:]^T + xpre[t] : M=512, N=512, K=512
        gemm_tf32<64, 32, 2, 2, 0><<<dim3(HID / 32, BATCH / 64), 128>>>(
            p_ctx, HID, HID, nullptr, 0, HID,
            Wc, EMB + HID, 512, nullptr, p_xpre + (size_t)t * BATCH * HID,
            p_x, HID, nullptr, 0);

        // gates+LSTM: [x,h] @ Wg^T ; fused pointwise, writes hw, g_c, g_hist[t]
        gemm_tf32<128, 64, 4, 2, 1><<<dim3((4 * HID) / 64, BATCH / 128), 256>>>(
            p_x, HID, HID, hr, HID, 2 * HID,
            p_Wg, 2 * HID, 0, nullptr, nullptr, nullptr, 0, hw, t);
    }

    // out[b,t,:] = hist @ Wo^T + bo : M=15360, N=96, K=512, permuted write
    gemm_tf32<128, 32, 4, 1, 2><<<dim3(NCLS / 32, (TT * BATCH) / 128), 128>>>(
        p_hist, HID, HID, nullptr, 0, HID,
        Wo, HID, 0, bo, nullptr, out, 0, nullptr, 0);
}